// round 9
// baseline (speedup 1.0000x reference)
#include <cuda_runtime.h>
#include <cuda_bf16.h>
#include <cstdint>

// Problem: B=32, N=1024, K=16, D=256, L=256
#define ROWS_TOTAL 32768
#define D_DIM 256
#define L_DIM 256
#define KNBR 16

#define TM 64                  // rows per CTA
#define KC 32                  // d-values per MMA chunk
#define NCHUNK 8
#define THREADS 256

// A: 64 rows x 512B (256 bf16), XOR-swizzled 16B units (no padding)
#define A_HI 0
#define A_LO 32768
// B: staged chunk, 256 rows x 64B data, pitch 80 (R8-proven)
#define PITCH 80
#define B_HI 65536
#define B_LO (B_HI + L_DIM * PITCH)              // 86016
#define SMEM_BYTES (B_LO + L_DIM * PITCH)        // 106496

// W^T bf16 hi/lo scratch, [n][k] row-major
__device__ __nv_bfloat16 g_wt_hi[L_DIM * D_DIM];
__device__ __nv_bfloat16 g_wt_lo[L_DIM * D_DIM];

__device__ __forceinline__ uint32_t smem_u32(const void* p) {
    uint32_t a;
    asm("{ .reg .u64 t; cvta.to.shared.u64 t, %1; cvt.u32.u64 %0, t; }" : "=r"(a) : "l"(p));
    return a;
}

__device__ __forceinline__ uint32_t bfpack(float a, float b) {
    unsigned short ua = __bfloat16_as_ushort(__float2bfloat16(a));
    unsigned short ub = __bfloat16_as_ushort(__float2bfloat16(b));
    return (uint32_t)ua | ((uint32_t)ub << 16);
}

__device__ __forceinline__ void ldsm_x4(uint32_t* r, uint32_t addr) {
    asm volatile("ldmatrix.sync.aligned.m8n8.x4.shared.b16 {%0,%1,%2,%3}, [%4];"
                 : "=r"(r[0]), "=r"(r[1]), "=r"(r[2]), "=r"(r[3]) : "r"(addr));
}

__device__ __forceinline__ void ldsm_x2(uint32_t* r, uint32_t addr) {
    asm volatile("ldmatrix.sync.aligned.m8n8.x2.shared.b16 {%0,%1}, [%2];"
                 : "=r"(r[0]), "=r"(r[1]) : "r"(addr));
}

__device__ __forceinline__ void hmma(float* c, const uint32_t* a, const uint32_t* b) {
    asm volatile(
        "mma.sync.aligned.m16n8k16.row.col.f32.bf16.bf16.f32 "
        "{%0,%1,%2,%3}, {%4,%5,%6,%7}, {%8,%9}, {%0,%1,%2,%3};"
        : "+f"(c[0]), "+f"(c[1]), "+f"(c[2]), "+f"(c[3])
        : "r"(a[0]), "r"(a[1]), "r"(a[2]), "r"(a[3]), "r"(b[0]), "r"(b[1]));
}

// ---------------- prep kernel: W[k][n] -> WT_hi/lo[n][k] bf16 ----------------
__global__ void prep_wt(const float* __restrict__ W) {
    int k = blockIdx.x;        // 256
    int n = threadIdx.x;       // 256
    float w = W[(size_t)k * L_DIM + n];
    __nv_bfloat16 hi = __float2bfloat16(w);
    float r = w - __bfloat162float(hi);
    g_wt_hi[(size_t)n * D_DIM + k] = hi;
    g_wt_lo[(size_t)n * D_DIM + k] = __float2bfloat16(r);
}

// ---------------- main fused kernel ----------------
__global__ void __launch_bounds__(THREADS, 2) gcn_kfull_kernel(
    const float* __restrict__ targets,
    const float* __restrict__ neighbors,
    const float* __restrict__ avec,
    float* __restrict__ out)
{
    extern __shared__ char smem[];
    const uint32_t sbase = smem_u32(smem);

    const int tid  = threadIdx.x;
    const int lane = tid & 31;
    const int w    = tid >> 5;
    const int row0 = blockIdx.x * TM;

    // reduction identity: 4 threads per row; thread q owns d-units uu ≡ q (mod 4)
    const int r   = tid >> 2;          // 0..63
    const int q   = tid & 3;           // 0..3
    const int row = row0 + r;

    // degree factor (4x redundant; trivial)
    const float* ap = avec + (size_t)row * (KNBR + 1);
    float fdeg = 0.f;
#pragma unroll
    for (int j = 0; j < KNBR + 1; j++) fdeg += ap[j];
    const float inv = (fdeg > 0.5f) ? (1.0f / fdeg) : 1.0f;

    const float* tgt = targets   + (size_t)row * D_DIM;
    const float* nb  = neighbors + (size_t)row * (KNBR * D_DIM);

    // ---- phase 1: full-row reduction, k-contiguous (DRAM page-friendly) ----
    float acc[64];                     // d = (4*jj+q)*8 + e  -> acc[8*jj+e]
#pragma unroll
    for (int jj = 0; jj < 8; jj++) {
        float4 v0 = *(const float4*)&tgt[(4 * jj + q) * 8];
        float4 v1 = *(const float4*)&tgt[(4 * jj + q) * 8 + 4];
        acc[8*jj+0] = v0.x; acc[8*jj+1] = v0.y; acc[8*jj+2] = v0.z; acc[8*jj+3] = v0.w;
        acc[8*jj+4] = v1.x; acc[8*jj+5] = v1.y; acc[8*jj+6] = v1.z; acc[8*jj+7] = v1.w;
    }
#pragma unroll 1
    for (int k = 0; k < KNBR; k++) {
        const float* src = nb + k * D_DIM;   // full 1KB row per warp, contiguous
#pragma unroll
        for (int jj = 0; jj < 8; jj++) {
            float4 v0 = __ldcs((const float4*)&src[(4 * jj + q) * 8]);
            float4 v1 = __ldcs((const float4*)&src[(4 * jj + q) * 8 + 4]);
            acc[8*jj+0] += v0.x; acc[8*jj+1] += v0.y; acc[8*jj+2] += v0.z; acc[8*jj+3] += v0.w;
            acc[8*jj+4] += v1.x; acc[8*jj+5] += v1.y; acc[8*jj+6] += v1.z; acc[8*jj+7] += v1.w;
        }
    }

    // scale, hi/lo split, swizzled store of complete A tiles
#pragma unroll
    for (int jj = 0; jj < 8; jj++) {
        float d[8], h[8];
#pragma unroll
        for (int e = 0; e < 8; e++) {
            d[e] = acc[8 * jj + e] * inv;
            h[e] = __bfloat162float(__float2bfloat16(d[e]));
        }
        uint4 hi, lo;
        hi.x = bfpack(d[0], d[1]); hi.y = bfpack(d[2], d[3]);
        hi.z = bfpack(d[4], d[5]); hi.w = bfpack(d[6], d[7]);
        lo.x = bfpack(d[0]-h[0], d[1]-h[1]); lo.y = bfpack(d[2]-h[2], d[3]-h[3]);
        lo.z = bfpack(d[4]-h[4], d[5]-h[5]); lo.w = bfpack(d[6]-h[6], d[7]-h[7]);

        uint32_t uu   = 4 * jj + q;                    // logical 16B unit (d/8)
        uint32_t off  = (uint32_t)r * 512 + ((uu ^ (r & 7)) * 16);
        *(uint4*)(smem + A_HI + off) = hi;
        *(uint4*)(smem + A_LO + off) = lo;
    }
    __syncthreads();

    // ---- phase 2: MMA over 8 d-chunks, B staged per chunk ----
    const int m0 = (w & 1) * 32;
    const int n0 = (w >> 1) * 64;

    float facc[2][8][4];
#pragma unroll
    for (int i = 0; i < 2; i++)
#pragma unroll
        for (int j = 0; j < 8; j++)
#pragma unroll
            for (int t = 0; t < 4; t++) facc[i][j][t] = 0.f;

    for (int c = 0; c < NCHUNK; c++) {
        if (c) __syncthreads();            // B buffer free (prev chunk reads done)

        // stage B chunk: WT hi/lo rows, 64B per row
#pragma unroll
        for (int i = 0; i < 8; i++) {
            int p   = i * 256 + tid;       // 0..2047 16B-pieces
            int mat = p >> 10;             // 0: hi, 1: lo
            int n   = (p >> 2) & 255;
            int kq  = p & 3;
            const __nv_bfloat16* src = (mat ? g_wt_lo : g_wt_hi) + (size_t)n * D_DIM + c * KC;
            uint4 v = ((const uint4*)src)[kq];
            *(uint4*)(smem + (mat ? B_LO : B_HI) + n * PITCH + kq * 16) = v;
        }
        __syncthreads();

#pragma unroll
        for (int ks = 0; ks < 2; ks++) {
            // A fragments from swizzled resident tiles
            uint32_t Ah[2][4], Al[2][4];
            const uint32_t cu = (uint32_t)(c * 4 + ks * 2 + ((lane & 16) ? 1 : 0));
#pragma unroll
            for (int mt = 0; mt < 2; mt++) {
                uint32_t arow = (uint32_t)(m0 + (lane & 15) + mt * 16);
                uint32_t aoff = arow * 512 + ((cu ^ (arow & 7)) * 16);
                ldsm_x4(Ah[mt], sbase + A_HI + aoff);
                ldsm_x4(Al[mt], sbase + A_LO + aoff);
            }

            const int kb = ks * 32;
            const uint32_t brow = (uint32_t)(n0 + (lane & 7));
            const uint32_t bcol = (uint32_t)(kb + ((lane & 8) ? 16 : 0));
#pragma unroll
            for (int nt = 0; nt < 8; nt++) {
                uint32_t Bh[2], Bl[2];
                uint32_t off = (brow + nt * 8) * PITCH + bcol;
                ldsm_x2(Bh, sbase + B_HI + off);
                ldsm_x2(Bl, sbase + B_LO + off);
#pragma unroll
                for (int mt = 0; mt < 2; mt++) {
                    hmma(facc[mt][nt], Ah[mt], Bh);
                    hmma(facc[mt][nt], Ah[mt], Bl);
                    hmma(facc[mt][nt], Al[mt], Bh);
                }
            }
        }
    }

    // ---- epilogue: relu + float2 stores (32B sectors fully used) ----
#pragma unroll
    for (int mt = 0; mt < 2; mt++) {
#pragma unroll
        for (int nt = 0; nt < 8; nt++) {
            const int mrow = row0 + m0 + mt * 16 + (lane >> 2);
            const int col  = n0 + nt * 8 + (lane & 3) * 2;
            float2 v0, v1;
            v0.x = fmaxf(facc[mt][nt][0], 0.f);
            v0.y = fmaxf(facc[mt][nt][1], 0.f);
            v1.x = fmaxf(facc[mt][nt][2], 0.f);
            v1.y = fmaxf(facc[mt][nt][3], 0.f);
            *(float2*)&out[(size_t)mrow * L_DIM + col]       = v0;
            *(float2*)&out[(size_t)(mrow + 8) * L_DIM + col] = v1;
        }
    }
}

extern "C" void kernel_launch(void* const* d_in, const int* in_sizes, int n_in,
                              void* d_out, int out_size)
{
    const float* targets   = (const float*)d_in[0];
    const float* neighbors = (const float*)d_in[1];
    const float* avec      = (const float*)d_in[2];
    const float* W         = (const float*)d_in[3];
    float* out             = (float*)d_out;

    (void)in_sizes; (void)n_in; (void)out_size;

    cudaFuncSetAttribute(gcn_kfull_kernel,
                         cudaFuncAttributeMaxDynamicSharedMemorySize, SMEM_BYTES);

    prep_wt<<<256, 256>>>(W);
    gcn_kfull_kernel<<<ROWS_TOTAL / TM, THREADS, SMEM_BYTES>>>(targets, neighbors, avec, out);
}

// round 10
// speedup vs baseline: 1.1725x; 1.1725x over previous
#include <cuda_runtime.h>
#include <cuda_bf16.h>
#include <cstdint>

// Problem: B=32, N=1024, K=16, D=256, L=256
#define ROWS_TOTAL 32768
#define D_DIM 256
#define L_DIM 256
#define KNBR 16

// ---------------- scratch ----------------
// S (reduced+normalized) as bf16 hi/lo, row-major [row][d]
__device__ __nv_bfloat16 g_s_hi[ROWS_TOTAL * D_DIM];
__device__ __nv_bfloat16 g_s_lo[ROWS_TOTAL * D_DIM];
// W^T bf16 hi/lo, [n][k] row-major
__device__ __nv_bfloat16 g_wt_hi[L_DIM * D_DIM];
__device__ __nv_bfloat16 g_wt_lo[L_DIM * D_DIM];

__device__ __forceinline__ uint32_t smem_u32(const void* p) {
    uint32_t a;
    asm("{ .reg .u64 t; cvta.to.shared.u64 t, %1; cvt.u32.u64 %0, t; }" : "=r"(a) : "l"(p));
    return a;
}

__device__ __forceinline__ uint32_t bfpack(float a, float b) {
    unsigned short ua = __bfloat16_as_ushort(__float2bfloat16(a));
    unsigned short ub = __bfloat16_as_ushort(__float2bfloat16(b));
    return (uint32_t)ua | ((uint32_t)ub << 16);
}

__device__ __forceinline__ void ldsm_x4(uint32_t* r, uint32_t addr) {
    asm volatile("ldmatrix.sync.aligned.m8n8.x4.shared.b16 {%0,%1,%2,%3}, [%4];"
                 : "=r"(r[0]), "=r"(r[1]), "=r"(r[2]), "=r"(r[3]) : "r"(addr));
}

__device__ __forceinline__ void ldsm_x2(uint32_t* r, uint32_t addr) {
    asm volatile("ldmatrix.sync.aligned.m8n8.x2.shared.b16 {%0,%1}, [%2];"
                 : "=r"(r[0]), "=r"(r[1]) : "r"(addr));
}

__device__ __forceinline__ void hmma(float* c, const uint32_t* a, const uint32_t* b) {
    asm volatile(
        "mma.sync.aligned.m16n8k16.row.col.f32.bf16.bf16.f32 "
        "{%0,%1,%2,%3}, {%4,%5,%6,%7}, {%8,%9}, {%0,%1,%2,%3};"
        : "+f"(c[0]), "+f"(c[1]), "+f"(c[2]), "+f"(c[3])
        : "r"(a[0]), "r"(a[1]), "r"(a[2]), "r"(a[3]), "r"(b[0]), "r"(b[1]));
}

// ---------------- prep: W[k][n] -> WT_hi/lo[n][k] bf16 ----------------
__global__ void prep_wt(const float* __restrict__ W) {
    int k = blockIdx.x;        // 256
    int n = threadIdx.x;       // 256
    float w = W[(size_t)k * L_DIM + n];
    __nv_bfloat16 hi = __float2bfloat16(w);
    float r = w - __bfloat162float(hi);
    g_wt_hi[(size_t)n * D_DIM + k] = hi;
    g_wt_lo[(size_t)n * D_DIM + k] = __float2bfloat16(r);
}

// ============ kernel A: high-occupancy streaming reduction ============
// warp per row; per k-step 2 contiguous 512B LDG.128; ~50 regs -> 40+ warps/SM
__global__ void __launch_bounds__(256, 5) gcn_reduce_kernel(
    const float* __restrict__ targets,
    const float* __restrict__ neighbors,
    const float* __restrict__ avec)
{
    const int wid  = threadIdx.x >> 5;
    const int lane = threadIdx.x & 31;
    const int row  = blockIdx.x * 8 + wid;

    // degree factor via warp reduce
    float av = (lane < KNBR + 1) ? avec[(size_t)row * (KNBR + 1) + lane] : 0.f;
#pragma unroll
    for (int off = 16; off; off >>= 1) av += __shfl_xor_sync(0xFFFFFFFFu, av, off);
    const float inv = (av > 0.5f) ? (1.0f / av) : 1.0f;

    const float4* tgt4 = (const float4*)(targets + (size_t)row * D_DIM);
    const float4* nb4  = (const float4*)(neighbors + (size_t)row * (KNBR * D_DIM));

    float4 a0 = tgt4[lane];          // d-units: lane (d = 4*lane ..)
    float4 a1 = tgt4[lane + 32];     // d-units: lane+32

#pragma unroll 4
    for (int k = 0; k < KNBR; k++) {
        const float4* src = nb4 + (size_t)k * 64;
        float4 v0 = __ldcs(&src[lane]);
        float4 v1 = __ldcs(&src[lane + 32]);
        a0.x += v0.x; a0.y += v0.y; a0.z += v0.z; a0.w += v0.w;
        a1.x += v1.x; a1.y += v1.y; a1.z += v1.z; a1.w += v1.w;
    }
    a0.x *= inv; a0.y *= inv; a0.z *= inv; a0.w *= inv;
    a1.x *= inv; a1.y *= inv; a1.z *= inv; a1.w *= inv;

    // hi/lo split, pack, write (default caching: keep S in L2 for kernel B)
    float d0[4] = {a0.x, a0.y, a0.z, a0.w};
    float d1[4] = {a1.x, a1.y, a1.z, a1.w};
    uint2 h0, l0, h1, l1;
    {
        float h[4];
#pragma unroll
        for (int e = 0; e < 4; e++) h[e] = __bfloat162float(__float2bfloat16(d0[e]));
        h0.x = bfpack(d0[0], d0[1]); h0.y = bfpack(d0[2], d0[3]);
        l0.x = bfpack(d0[0]-h[0], d0[1]-h[1]); l0.y = bfpack(d0[2]-h[2], d0[3]-h[3]);
#pragma unroll
        for (int e = 0; e < 4; e++) h[e] = __bfloat162float(__float2bfloat16(d1[e]));
        h1.x = bfpack(d1[0], d1[1]); h1.y = bfpack(d1[2], d1[3]);
        l1.x = bfpack(d1[0]-h[0], d1[1]-h[1]); l1.y = bfpack(d1[2]-h[2], d1[3]-h[3]);
    }
    uint2* shi = (uint2*)(g_s_hi + (size_t)row * D_DIM);
    uint2* slo = (uint2*)(g_s_lo + (size_t)row * D_DIM);
    shi[lane]      = h0;  shi[lane + 32] = h1;
    slo[lane]      = l0;  slo[lane + 32] = l1;
}

// ============ kernel B: HMMA GEMM (R8 phase-2, A staged from S) ============
#define TM 64
#define KC 32
#define NCHUNK 8
#define PITCH 80
#define A_HI 0
#define A_LO (A_HI + TM * PITCH)                 // 5120
#define B_HI (A_LO + TM * PITCH)                 // 10240
#define B_LO (B_HI + L_DIM * PITCH)              // 30720
#define SMEM_BYTES (B_LO + L_DIM * PITCH)        // 51200

__global__ void __launch_bounds__(256, 2) gcn_gemm_kernel(float* __restrict__ out)
{
    extern __shared__ char smem[];
    const uint32_t sbase = smem_u32(smem);

    const int tid  = threadIdx.x;
    const int lane = tid & 31;
    const int w    = tid >> 5;
    const int row0 = blockIdx.x * TM;

    const int m0 = (w & 1) * 32;
    const int n0 = (w >> 1) * 64;

    float acc[2][8][4];
#pragma unroll
    for (int i = 0; i < 2; i++)
#pragma unroll
        for (int j = 0; j < 8; j++)
#pragma unroll
            for (int t = 0; t < 4; t++) acc[i][j][t] = 0.f;

    for (int c = 0; c < NCHUNK; c++) {
        if (c) __syncthreads();

        // stage A chunk: 64 rows x 32 bf16 (64B) per matrix, 512 16B-pieces
#pragma unroll
        for (int i = 0; i < 2; i++) {
            int p   = i * 256 + tid;
            int mat = p >> 8;                  // 0: hi, 1: lo
            int r   = (p >> 2) & 63;
            int kq  = p & 3;
            const __nv_bfloat16* src =
                (mat ? g_s_lo : g_s_hi) + (size_t)(row0 + r) * D_DIM + c * KC;
            uint4 v = ((const uint4*)src)[kq];
            *(uint4*)(smem + (mat ? A_LO : A_HI) + r * PITCH + kq * 16) = v;
        }
        // stage B chunk: WT hi/lo rows, 64B per row, 2048 16B-pieces
#pragma unroll
        for (int i = 0; i < 8; i++) {
            int p   = i * 256 + tid;
            int mat = p >> 10;
            int n   = (p >> 2) & 255;
            int kq  = p & 3;
            const __nv_bfloat16* src =
                (mat ? g_wt_lo : g_wt_hi) + (size_t)n * D_DIM + c * KC;
            uint4 v = ((const uint4*)src)[kq];
            *(uint4*)(smem + (mat ? B_LO : B_HI) + n * PITCH + kq * 16) = v;
        }
        __syncthreads();

#pragma unroll
        for (int ks = 0; ks < 2; ks++) {
            const int kb = ks * 32;
            uint32_t Ah[2][4], Al[2][4];
            const uint32_t arow = m0 + (lane & 15);
            const uint32_t acol = kb + ((lane & 16) ? 16 : 0);
#pragma unroll
            for (int mt = 0; mt < 2; mt++) {
                uint32_t off = (arow + mt * 16) * PITCH + acol;
                ldsm_x4(Ah[mt], sbase + A_HI + off);
                ldsm_x4(Al[mt], sbase + A_LO + off);
            }
            const uint32_t brow = n0 + (lane & 7);
            const uint32_t bcol = kb + ((lane & 8) ? 16 : 0);
#pragma unroll
            for (int nt = 0; nt < 8; nt++) {
                uint32_t Bh[2], Bl[2];
                uint32_t off = (brow + nt * 8) * PITCH + bcol;
                ldsm_x2(Bh, sbase + B_HI + off);
                ldsm_x2(Bl, sbase + B_LO + off);
#pragma unroll
                for (int mt = 0; mt < 2; mt++) {
                    hmma(acc[mt][nt], Ah[mt], Bh);
                    hmma(acc[mt][nt], Ah[mt], Bl);
                    hmma(acc[mt][nt], Al[mt], Bh);
                }
            }
        }
    }

    // epilogue: relu + float2 stores
#pragma unroll
    for (int mt = 0; mt < 2; mt++) {
#pragma unroll
        for (int nt = 0; nt < 8; nt++) {
            const int mrow = row0 + m0 + mt * 16 + (lane >> 2);
            const int col  = n0 + nt * 8 + (lane & 3) * 2;
            float2 v0, v1;
            v0.x = fmaxf(acc[mt][nt][0], 0.f);
            v0.y = fmaxf(acc[mt][nt][1], 0.f);
            v1.x = fmaxf(acc[mt][nt][2], 0.f);
            v1.y = fmaxf(acc[mt][nt][3], 0.f);
            *(float2*)&out[(size_t)mrow * L_DIM + col]       = v0;
            *(float2*)&out[(size_t)(mrow + 8) * L_DIM + col] = v1;
        }
    }
}

extern "C" void kernel_launch(void* const* d_in, const int* in_sizes, int n_in,
                              void* d_out, int out_size)
{
    const float* targets   = (const float*)d_in[0];
    const float* neighbors = (const float*)d_in[1];
    const float* avec      = (const float*)d_in[2];
    const float* W         = (const float*)d_in[3];
    float* out             = (float*)d_out;

    (void)in_sizes; (void)n_in; (void)out_size;

    cudaFuncSetAttribute(gcn_gemm_kernel,
                         cudaFuncAttributeMaxDynamicSharedMemorySize, SMEM_BYTES);

    prep_wt<<<256, 256>>>(W);
    gcn_reduce_kernel<<<ROWS_TOTAL / 8, 256>>>(targets, neighbors, avec);
    gcn_gemm_kernel<<<ROWS_TOTAL / TM, 256, SMEM_BYTES>>>(out);
}

// round 11
// speedup vs baseline: 1.2248x; 1.0446x over previous
#include <cuda_runtime.h>
#include <cuda_bf16.h>
#include <cstdint>

// Problem: B=32, N=1024, K=16, D=256, L=256
#define ROWS_TOTAL 32768
#define D_DIM 256
#define L_DIM 256
#define KNBR 16

// ---------------- scratch ----------------
__device__ float g_s[ROWS_TOTAL * D_DIM];            // reduced+normalized S, fp32
__device__ __nv_bfloat16 g_wt_hi[L_DIM * D_DIM];     // W^T hi, [n][k]
__device__ __nv_bfloat16 g_wt_lo[L_DIM * D_DIM];     // W^T lo, [n][k]

__device__ __forceinline__ uint32_t smem_u32(const void* p) {
    uint32_t a;
    asm("{ .reg .u64 t; cvta.to.shared.u64 t, %1; cvt.u32.u64 %0, t; }" : "=r"(a) : "l"(p));
    return a;
}

__device__ __forceinline__ uint32_t bfpack(float a, float b) {
    unsigned short ua = __bfloat16_as_ushort(__float2bfloat16(a));
    unsigned short ub = __bfloat16_as_ushort(__float2bfloat16(b));
    return (uint32_t)ua | ((uint32_t)ub << 16);
}

__device__ __forceinline__ void ldsm_x4(uint32_t* r, uint32_t addr) {
    asm volatile("ldmatrix.sync.aligned.m8n8.x4.shared.b16 {%0,%1,%2,%3}, [%4];"
                 : "=r"(r[0]), "=r"(r[1]), "=r"(r[2]), "=r"(r[3]) : "r"(addr));
}

__device__ __forceinline__ void ldsm_x2(uint32_t* r, uint32_t addr) {
    asm volatile("ldmatrix.sync.aligned.m8n8.x2.shared.b16 {%0,%1}, [%2];"
                 : "=r"(r[0]), "=r"(r[1]) : "r"(addr));
}

__device__ __forceinline__ void hmma(float* c, const uint32_t* a, const uint32_t* b) {
    asm volatile(
        "mma.sync.aligned.m16n8k16.row.col.f32.bf16.bf16.f32 "
        "{%0,%1,%2,%3}, {%4,%5,%6,%7}, {%8,%9}, {%0,%1,%2,%3};"
        : "+f"(c[0]), "+f"(c[1]), "+f"(c[2]), "+f"(c[3])
        : "r"(a[0]), "r"(a[1]), "r"(a[2]), "r"(a[3]), "r"(b[0]), "r"(b[1]));
}

// ---------- prep: W[k][n] -> WT_hi/lo[n][k], smem-tile transpose ----------
// block b owns k in [b*16, b*16+16); coalesced loads, 32B-per-thread writes.
__global__ void __launch_bounds__(256) prep_wt(const float* __restrict__ W) {
    __shared__ float tile[16][L_DIM];
    const int b = blockIdx.x;             // 16 blocks
    const int tid = threadIdx.x;
#pragma unroll
    for (int i = 0; i < 16; i++) {        // 16 rows x 256 floats, coalesced
        tile[i][tid] = W[(size_t)(b * 16 + i) * L_DIM + tid];
    }
    __syncthreads();
    const int n = tid;                    // one n per thread
    uint2 hi[2], lo[2];
    float d[16], h[16];
#pragma unroll
    for (int i = 0; i < 16; i++) {
        d[i] = tile[i][n];
        h[i] = __bfloat162float(__float2bfloat16(d[i]));
    }
#pragma unroll
    for (int g = 0; g < 2; g++) {
        hi[g].x = bfpack(d[g*8+0], d[g*8+1]) , hi[g].x = bfpack(d[g*8+0], d[g*8+1]);
        hi[g].x = bfpack(d[g*8+0], d[g*8+1]);
        hi[g].y = bfpack(d[g*8+2], d[g*8+3]);
        lo[g].x = bfpack(d[g*8+0]-h[g*8+0], d[g*8+1]-h[g*8+1]);
        lo[g].y = bfpack(d[g*8+2]-h[g*8+2], d[g*8+3]-h[g*8+3]);
        uint2 hi2, lo2;
        hi2.x = bfpack(d[g*8+4], d[g*8+5]);
        hi2.y = bfpack(d[g*8+6], d[g*8+7]);
        lo2.x = bfpack(d[g*8+4]-h[g*8+4], d[g*8+5]-h[g*8+5]);
        lo2.y = bfpack(d[g*8+6]-h[g*8+6], d[g*8+7]-h[g*8+7]);
        uint4* dsth = (uint4*)(g_wt_hi + (size_t)n * D_DIM + b * 16 + g * 8);
        uint4* dstl = (uint4*)(g_wt_lo + (size_t)n * D_DIM + b * 16 + g * 8);
        *dsth = make_uint4(hi[g].x, hi[g].y, hi2.x, hi2.y);
        *dstl = make_uint4(lo[g].x, lo[g].y, lo2.x, lo2.y);
    }
}

// ============ kernel A: streaming reduction, warp per half-row ============
// 1 LDG.128 per lane per k; ~32 regs -> 56 warps/SM; S stays in L2 for GEMM.
__global__ void __launch_bounds__(256, 7) gcn_reduce_kernel(
    const float* __restrict__ targets,
    const float* __restrict__ neighbors,
    const float* __restrict__ avec)
{
    const int wid  = threadIdx.x >> 5;
    const int lane = threadIdx.x & 31;
    const int h    = blockIdx.x * 8 + wid;   // half-row id, 65536 total
    const int row  = h >> 1;
    const int half = h & 1;

    // degree factor via warp reduce (2x redundant per row; trivial)
    float av = (lane < KNBR + 1) ? avec[(size_t)row * (KNBR + 1) + lane] : 0.f;
#pragma unroll
    for (int off = 16; off; off >>= 1) av += __shfl_xor_sync(0xFFFFFFFFu, av, off);
    const float inv = (av > 0.5f) ? (1.0f / av) : 1.0f;

    const float4* t4 = (const float4*)targets   + (size_t)row * 64  + half * 32 + lane;
    const float4* n4 = (const float4*)neighbors + (size_t)row * 1024 + half * 32 + lane;

    float4 acc = *t4;
#pragma unroll
    for (int k = 0; k < KNBR; k += 4) {      // 4 batched independent LDG.128
        float4 v0 = __ldcs(n4 + (size_t)(k + 0) * 64);
        float4 v1 = __ldcs(n4 + (size_t)(k + 1) * 64);
        float4 v2 = __ldcs(n4 + (size_t)(k + 2) * 64);
        float4 v3 = __ldcs(n4 + (size_t)(k + 3) * 64);
        acc.x += v0.x; acc.y += v0.y; acc.z += v0.z; acc.w += v0.w;
        acc.x += v1.x; acc.y += v1.y; acc.z += v1.z; acc.w += v1.w;
        acc.x += v2.x; acc.y += v2.y; acc.z += v2.z; acc.w += v2.w;
        acc.x += v3.x; acc.y += v3.y; acc.z += v3.z; acc.w += v3.w;
    }
    acc.x *= inv; acc.y *= inv; acc.z *= inv; acc.w *= inv;

    ((float4*)g_s)[(size_t)row * 64 + half * 32 + lane] = acc;   // default: L2-resident
}

// ============ kernel B: HMMA GEMM (proven R10 core; A from fp32 S) ============
#define TM 64
#define KC 32
#define NCHUNK 8
#define PITCH 80
#define A_HI 0
#define A_LO (A_HI + TM * PITCH)                 // 5120
#define B_HI (A_LO + TM * PITCH)                 // 10240
#define B_LO (B_HI + L_DIM * PITCH)              // 30720
#define SMEM_BYTES (B_LO + L_DIM * PITCH)        // 51200

__global__ void __launch_bounds__(256, 2) gcn_gemm_kernel(float* __restrict__ out)
{
    extern __shared__ char smem[];
    const uint32_t sbase = smem_u32(smem);

    const int tid  = threadIdx.x;
    const int lane = tid & 31;
    const int w    = tid >> 5;
    const int row0 = blockIdx.x * TM;

    const int m0 = (w & 1) * 32;
    const int n0 = (w >> 1) * 64;

    float acc[2][8][4];
#pragma unroll
    for (int i = 0; i < 2; i++)
#pragma unroll
        for (int j = 0; j < 8; j++)
#pragma unroll
            for (int t = 0; t < 4; t++) acc[i][j][t] = 0.f;

    for (int c = 0; c < NCHUNK; c++) {
        if (c) __syncthreads();

        // stage A chunk from fp32 S (L2-resident): 512 float4 pieces, split hi/lo
#pragma unroll
        for (int i = 0; i < 2; i++) {
            int p  = i * 256 + tid;            // 0..511
            int r  = p >> 3;                   // 64 rows
            int kq = p & 7;                    // 8 float4 per 32-k row
            float4 v = *(const float4*)(g_s + (size_t)(row0 + r) * D_DIM + c * KC + kq * 4);
            float hx = __bfloat162float(__float2bfloat16(v.x));
            float hy = __bfloat162float(__float2bfloat16(v.y));
            float hz = __bfloat162float(__float2bfloat16(v.z));
            float hw = __bfloat162float(__float2bfloat16(v.w));
            uint2 hi2, lo2;
            hi2.x = bfpack(v.x, v.y);       hi2.y = bfpack(v.z, v.w);
            lo2.x = bfpack(v.x - hx, v.y - hy);
            lo2.y = bfpack(v.z - hz, v.w - hw);
            *(uint2*)(smem + A_HI + r * PITCH + kq * 8) = hi2;
            *(uint2*)(smem + A_LO + r * PITCH + kq * 8) = lo2;
        }
        // stage B chunk: WT hi/lo rows, 64B per row, 2048 16B-pieces
#pragma unroll
        for (int i = 0; i < 8; i++) {
            int p   = i * 256 + tid;
            int mat = p >> 10;
            int n   = (p >> 2) & 255;
            int kq  = p & 3;
            const __nv_bfloat16* src =
                (mat ? g_wt_lo : g_wt_hi) + (size_t)n * D_DIM + c * KC;
            uint4 v = ((const uint4*)src)[kq];
            *(uint4*)(smem + (mat ? B_LO : B_HI) + n * PITCH + kq * 16) = v;
        }
        __syncthreads();

#pragma unroll
        for (int ks = 0; ks < 2; ks++) {
            const int kb = ks * 32;
            uint32_t Ah[2][4], Al[2][4];
            const uint32_t arow = m0 + (lane & 15);
            const uint32_t acol = kb + ((lane & 16) ? 16 : 0);
#pragma unroll
            for (int mt = 0; mt < 2; mt++) {
                uint32_t off = (arow + mt * 16) * PITCH + acol;
                ldsm_x4(Ah[mt], sbase + A_HI + off);
                ldsm_x4(Al[mt], sbase + A_LO + off);
            }
            const uint32_t brow = n0 + (lane & 7);
            const uint32_t bcol = kb + ((lane & 8) ? 16 : 0);
#pragma unroll
            for (int nt = 0; nt < 8; nt++) {
                uint32_t Bh[2], Bl[2];
                uint32_t off = (brow + nt * 8) * PITCH + bcol;
                ldsm_x2(Bh, sbase + B_HI + off);
                ldsm_x2(Bl, sbase + B_LO + off);
#pragma unroll
                for (int mt = 0; mt < 2; mt++) {
                    hmma(acc[mt][nt], Ah[mt], Bh);
                    hmma(acc[mt][nt], Ah[mt], Bl);
                    hmma(acc[mt][nt], Al[mt], Bh);
                }
            }
        }
    }

    // epilogue: relu + float2 stores
#pragma unroll
    for (int mt = 0; mt < 2; mt++) {
#pragma unroll
        for (int nt = 0; nt < 8; nt++) {
            const int mrow = row0 + m0 + mt * 16 + (lane >> 2);
            const int col  = n0 + nt * 8 + (lane & 3) * 2;
            float2 v0, v1;
            v0.x = fmaxf(acc[mt][nt][0], 0.f);
            v0.y = fmaxf(acc[mt][nt][1], 0.f);
            v1.x = fmaxf(acc[mt][nt][2], 0.f);
            v1.y = fmaxf(acc[mt][nt][3], 0.f);
            *(float2*)&out[(size_t)mrow * L_DIM + col]       = v0;
            *(float2*)&out[(size_t)(mrow + 8) * L_DIM + col] = v1;
        }
    }
}

extern "C" void kernel_launch(void* const* d_in, const int* in_sizes, int n_in,
                              void* d_out, int out_size)
{
    const float* targets   = (const float*)d_in[0];
    const float* neighbors = (const float*)d_in[1];
    const float* avec      = (const float*)d_in[2];
    const float* W         = (const float*)d_in[3];
    float* out             = (float*)d_out;

    (void)in_sizes; (void)n_in; (void)out_size;

    cudaFuncSetAttribute(gcn_gemm_kernel,
                         cudaFuncAttributeMaxDynamicSharedMemorySize, SMEM_BYTES);

    prep_wt<<<16, 256>>>(W);
    gcn_reduce_kernel<<<ROWS_TOTAL * 2 / 8, 256>>>(targets, neighbors, avec);
    gcn_gemm_kernel<<<ROWS_TOTAL / TM, 256, SMEM_BYTES>>>(out);
}

// round 12
// speedup vs baseline: 1.2411x; 1.0133x over previous
#include <cuda_runtime.h>
#include <cuda_bf16.h>
#include <cstdint>

// Problem: B=32, N=1024, K=16, D=256, L=256
#define ROWS_TOTAL 32768
#define D_DIM 256
#define L_DIM 256
#define KNBR 16

// ---------------- scratch ----------------
__device__ float g_s[ROWS_TOTAL * D_DIM];            // reduced+normalized S, fp32
__device__ __nv_bfloat16 g_wt_hi[L_DIM * D_DIM];     // W^T hi, [n][k]
__device__ __nv_bfloat16 g_wt_lo[L_DIM * D_DIM];     // W^T lo, [n][k]

__device__ __forceinline__ uint32_t smem_u32(const void* p) {
    uint32_t a;
    asm("{ .reg .u64 t; cvta.to.shared.u64 t, %1; cvt.u32.u64 %0, t; }" : "=r"(a) : "l"(p));
    return a;
}

__device__ __forceinline__ uint32_t bfpack(float a, float b) {
    unsigned short ua = __bfloat16_as_ushort(__float2bfloat16(a));
    unsigned short ub = __bfloat16_as_ushort(__float2bfloat16(b));
    return (uint32_t)ua | ((uint32_t)ub << 16);
}

__device__ __forceinline__ void ldsm_x4(uint32_t* r, uint32_t addr) {
    asm volatile("ldmatrix.sync.aligned.m8n8.x4.shared.b16 {%0,%1,%2,%3}, [%4];"
                 : "=r"(r[0]), "=r"(r[1]), "=r"(r[2]), "=r"(r[3]) : "r"(addr));
}

__device__ __forceinline__ void ldsm_x2(uint32_t* r, uint32_t addr) {
    asm volatile("ldmatrix.sync.aligned.m8n8.x2.shared.b16 {%0,%1}, [%2];"
                 : "=r"(r[0]), "=r"(r[1]) : "r"(addr));
}

__device__ __forceinline__ void hmma(float* c, const uint32_t* a, const uint32_t* b) {
    asm volatile(
        "mma.sync.aligned.m16n8k16.row.col.f32.bf16.bf16.f32 "
        "{%0,%1,%2,%3}, {%4,%5,%6,%7}, {%8,%9}, {%0,%1,%2,%3};"
        : "+f"(c[0]), "+f"(c[1]), "+f"(c[2]), "+f"(c[3])
        : "r"(a[0]), "r"(a[1]), "r"(a[2]), "r"(a[3]), "r"(b[0]), "r"(b[1]));
}

// ============ kernel A: streaming reduction + embedded W prep ============
// warp per half-row; blocks 0..15 additionally transpose/split a 16-k W slice.
__global__ void __launch_bounds__(256, 7) gcn_reduce_kernel(
    const float* __restrict__ targets,
    const float* __restrict__ neighbors,
    const float* __restrict__ avec,
    const float* __restrict__ W)
{
    __shared__ float wtile[16][L_DIM];   // 16KB; occupancy 7*16=112KB OK

    const int wid  = threadIdx.x >> 5;
    const int lane = threadIdx.x & 31;
    const int h    = blockIdx.x * 8 + wid;   // half-row id, 65536 total
    const int row  = h >> 1;
    const int half = h & 1;

    // degree factor via warp reduce (2x redundant per row; trivial)
    float av = (lane < KNBR + 1) ? avec[(size_t)row * (KNBR + 1) + lane] : 0.f;
#pragma unroll
    for (int off = 16; off; off >>= 1) av += __shfl_xor_sync(0xFFFFFFFFu, av, off);
    const float inv = (av > 0.5f) ? (1.0f / av) : 1.0f;

    const float4* t4 = (const float4*)targets   + (size_t)row * 64   + half * 32 + lane;
    const float4* n4 = (const float4*)neighbors + (size_t)row * 1024 + half * 32 + lane;

    float4 acc = *t4;
#pragma unroll
    for (int k = 0; k < KNBR; k += 4) {      // 4 batched independent LDG.128
        float4 v0 = __ldcs(n4 + (size_t)(k + 0) * 64);
        float4 v1 = __ldcs(n4 + (size_t)(k + 1) * 64);
        float4 v2 = __ldcs(n4 + (size_t)(k + 2) * 64);
        float4 v3 = __ldcs(n4 + (size_t)(k + 3) * 64);
        acc.x += v0.x; acc.y += v0.y; acc.z += v0.z; acc.w += v0.w;
        acc.x += v1.x; acc.y += v1.y; acc.z += v1.z; acc.w += v1.w;
        acc.x += v2.x; acc.y += v2.y; acc.z += v2.z; acc.w += v2.w;
        acc.x += v3.x; acc.y += v3.y; acc.z += v3.z; acc.w += v3.w;
    }
    acc.x *= inv; acc.y *= inv; acc.z *= inv; acc.w *= inv;

    ((float4*)g_s)[(size_t)row * 64 + half * 32 + lane] = acc;   // L2-resident for GEMM

    // ---- blocks 0..15: prep W slice [b*16 .. b*16+16) -> WT hi/lo ----
    if (blockIdx.x < 16) {
        const int b   = blockIdx.x;
        const int tid = threadIdx.x;
#pragma unroll
        for (int i = 0; i < 16; i++)
            wtile[i][tid] = W[(size_t)(b * 16 + i) * L_DIM + tid];
        __syncthreads();
        const int n = tid;
#pragma unroll
        for (int g = 0; g < 2; g++) {        // 8 k-values per group (low reg pressure)
            float d[8], hh[8];
#pragma unroll
            for (int e = 0; e < 8; e++) {
                d[e]  = wtile[g * 8 + e][n];
                hh[e] = __bfloat162float(__float2bfloat16(d[e]));
            }
            uint4 hi4, lo4;
            hi4.x = bfpack(d[0], d[1]);           hi4.y = bfpack(d[2], d[3]);
            hi4.z = bfpack(d[4], d[5]);           hi4.w = bfpack(d[6], d[7]);
            lo4.x = bfpack(d[0]-hh[0], d[1]-hh[1]); lo4.y = bfpack(d[2]-hh[2], d[3]-hh[3]);
            lo4.z = bfpack(d[4]-hh[4], d[5]-hh[5]); lo4.w = bfpack(d[6]-hh[6], d[7]-hh[7]);
            *(uint4*)(g_wt_hi + (size_t)n * D_DIM + b * 16 + g * 8) = hi4;
            *(uint4*)(g_wt_lo + (size_t)n * D_DIM + b * 16 + g * 8) = lo4;
        }
    }
}

// ============ kernel B: HMMA GEMM, TM=128 (halved W re-read traffic) ============
#define TM 128
#define KC 32
#define NCHUNK 8
#define PITCH 80
#define A_HI 0
#define A_LO (A_HI + TM * PITCH)                 // 10240
#define B_HI (A_LO + TM * PITCH)                 // 20480
#define B_LO (B_HI + L_DIM * PITCH)              // 40960
#define SMEM_BYTES (B_LO + L_DIM * PITCH)        // 61440
#define GTHREADS 512

__global__ void __launch_bounds__(GTHREADS, 1) gcn_gemm_kernel(float* __restrict__ out)
{
    extern __shared__ char smem[];
    const uint32_t sbase = smem_u32(smem);

    const int tid  = threadIdx.x;
    const int lane = tid & 31;
    const int w    = tid >> 5;                 // 0..15
    const int row0 = blockIdx.x * TM;

    const int m0 = (w & 3) * 32;               // 4 m-groups
    const int n0 = (w >> 2) * 64;              // 4 n-groups

    float acc[2][8][4];
#pragma unroll
    for (int i = 0; i < 2; i++)
#pragma unroll
        for (int j = 0; j < 8; j++)
#pragma unroll
            for (int t = 0; t < 4; t++) acc[i][j][t] = 0.f;

    for (int c = 0; c < NCHUNK; c++) {
        if (c) __syncthreads();

        // stage A chunk from fp32 S (L2-resident): 1024 float4 pieces, split hi/lo
#pragma unroll
        for (int i = 0; i < 2; i++) {
            int p  = i * GTHREADS + tid;       // 0..1023
            int r  = p >> 3;                   // 128 rows
            int kq = p & 7;                    // 8 float4 per 32-k row
            float4 v = *(const float4*)(g_s + (size_t)(row0 + r) * D_DIM + c * KC + kq * 4);
            float hx = __bfloat162float(__float2bfloat16(v.x));
            float hy = __bfloat162float(__float2bfloat16(v.y));
            float hz = __bfloat162float(__float2bfloat16(v.z));
            float hw = __bfloat162float(__float2bfloat16(v.w));
            uint2 hi2, lo2;
            hi2.x = bfpack(v.x, v.y);       hi2.y = bfpack(v.z, v.w);
            lo2.x = bfpack(v.x - hx, v.y - hy);
            lo2.y = bfpack(v.z - hz, v.w - hw);
            *(uint2*)(smem + A_HI + r * PITCH + kq * 8) = hi2;
            *(uint2*)(smem + A_LO + r * PITCH + kq * 8) = lo2;
        }
        // stage B chunk: WT hi/lo rows, 64B per row, 2048 16B-pieces
#pragma unroll
        for (int i = 0; i < 4; i++) {
            int p   = i * GTHREADS + tid;      // 0..2047
            int mat = p >> 10;                 // 0: hi, 1: lo
            int n   = (p >> 2) & 255;
            int kq  = p & 3;
            const __nv_bfloat16* src =
                (mat ? g_wt_lo : g_wt_hi) + (size_t)n * D_DIM + c * KC;
            uint4 v = ((const uint4*)src)[kq];
            *(uint4*)(smem + (mat ? B_LO : B_HI) + n * PITCH + kq * 16) = v;
        }
        __syncthreads();

#pragma unroll
        for (int ks = 0; ks < 2; ks++) {
            const int kb = ks * 32;
            uint32_t Ah[2][4], Al[2][4];
            const uint32_t arow = m0 + (lane & 15);
            const uint32_t acol = kb + ((lane & 16) ? 16 : 0);
#pragma unroll
            for (int mt = 0; mt < 2; mt++) {
                uint32_t off = (arow + mt * 16) * PITCH + acol;
                ldsm_x4(Ah[mt], sbase + A_HI + off);
                ldsm_x4(Al[mt], sbase + A_LO + off);
            }
            const uint32_t brow = n0 + (lane & 7);
            const uint32_t bcol = kb + ((lane & 8) ? 16 : 0);
#pragma unroll
            for (int nt = 0; nt < 8; nt++) {
                uint32_t Bh[2], Bl[2];
                uint32_t off = (brow + nt * 8) * PITCH + bcol;
                ldsm_x2(Bh, sbase + B_HI + off);
                ldsm_x2(Bl, sbase + B_LO + off);
#pragma unroll
                for (int mt = 0; mt < 2; mt++) {
                    hmma(acc[mt][nt], Ah[mt], Bh);
                    hmma(acc[mt][nt], Ah[mt], Bl);
                    hmma(acc[mt][nt], Al[mt], Bh);
                }
            }
        }
    }

    // epilogue: relu + float2 stores
#pragma unroll
    for (int mt = 0; mt < 2; mt++) {
#pragma unroll
        for (int nt = 0; nt < 8; nt++) {
            const int mrow = row0 + m0 + mt * 16 + (lane >> 2);
            const int col  = n0 + nt * 8 + (lane & 3) * 2;
            float2 v0, v1;
            v0.x = fmaxf(acc[mt][nt][0], 0.f);
            v0.y = fmaxf(acc[mt][nt][1], 0.f);
            v1.x = fmaxf(acc[mt][nt][2], 0.f);
            v1.y = fmaxf(acc[mt][nt][3], 0.f);
            *(float2*)&out[(size_t)mrow * L_DIM + col]       = v0;
            *(float2*)&out[(size_t)(mrow + 8) * L_DIM + col] = v1;
        }
    }
}

extern "C" void kernel_launch(void* const* d_in, const int* in_sizes, int n_in,
                              void* d_out, int out_size)
{
    const float* targets   = (const float*)d_in[0];
    const float* neighbors = (const float*)d_in[1];
    const float* avec      = (const float*)d_in[2];
    const float* W         = (const float*)d_in[3];
    float* out             = (float*)d_out;

    (void)in_sizes; (void)n_in; (void)out_size;

    cudaFuncSetAttribute(gcn_gemm_kernel,
                         cudaFuncAttributeMaxDynamicSharedMemorySize, SMEM_BYTES);

    gcn_reduce_kernel<<<ROWS_TOTAL * 2 / 8, 256>>>(targets, neighbors, avec, W);
    gcn_gemm_kernel<<<ROWS_TOTAL / TM, GTHREADS, SMEM_BYTES>>>(out);
}